// round 16
// baseline (speedup 1.0000x reference)
#include <cuda_runtime.h>
#include <float.h>

// x: [B=64, N=4096, D=1024] fp32. Per (b,d): top-16 along N, then mean -> out [B, D].
//
// 2-way row split: thread pair (t, t+64) in a block covers one column, rows
// [0,2048) and [2048,4096). 131072 threads total -> ~2x occupancy vs 1/col.
// Each thread keeps a sorted-descending top-16 in registers, SEEDED with
// T=2.1: inserts only fire for v > 2.1 until the running 16th exceeds it,
// cutting insert-chain executions ~35%. Unconditional correctness: if a lane
// recorded <16 inserts (rare: ~2e-4/half-col), it rescans its half with -inf.
// Merge: top-16 multiset of two sorted 16-arrays = {max(a[j], b[15-j])}
// (bitonic selection identity) -> 16 FMNMX + sum, order irrelevant for mean.

#define B_DIM 64
#define N_DIM 4096
#define D_DIM 1024
#define K_TOP 16
#define HALF_N (N_DIM / 2)          // 2048 rows per thread
#define COLS_PER_BLK 64
#define TPB 128                     // 64 lower-half + 64 upper-half threads
#define NBLK (B_DIM * D_DIM / COLS_PER_BLK)   // 1024
#define U 16
#define NBATCH (HALF_N / U)         // 128
#define T_INIT 2.1f

__device__ __forceinline__ void load_batch(float* __restrict__ buf,
                                           const float* __restrict__ p) {
#pragma unroll
    for (int u = 0; u < U; ++u)
        buf[u] = __ldcs(p + (size_t)u * D_DIM);
}

__device__ __forceinline__ void insert_sorted(float* __restrict__ top, float v) {
    // Level-parallel insert; reads OLD top only. Precondition: v > top[K-1].
    float nt[K_TOP];
    nt[0] = fmaxf(top[0], v);
#pragma unroll
    for (int j = 1; j < K_TOP; ++j)
        nt[j] = fmaxf(top[j], fminf(top[j - 1], v));
#pragma unroll
    for (int j = 0; j < K_TOP; ++j) top[j] = nt[j];
}

__device__ __forceinline__ void process_batch(float* __restrict__ top,
                                              const float* __restrict__ buf,
                                              int& cnt) {
#pragma unroll
    for (int u = 0; u < U; ++u) {
        float v = buf[u];
        if (v > top[K_TOP - 1]) {
            insert_sorted(top, v);
            ++cnt;
        }
    }
}

__global__ __launch_bounds__(TPB, 8)
void topk_mean_kernel(const float* __restrict__ x, float* __restrict__ out) {
    __shared__ float s_top[COLS_PER_BLK][K_TOP + 1];   // +1 pad: conflict-free reads

    const int tid = threadIdx.x;
    const int half = tid >> 6;           // 0: rows [0,2048), 1: rows [2048,4096)
    const int cidx = tid & 63;
    const int col = blockIdx.x * COLS_PER_BLK + cidx;  // 0..65535
    const int b = col >> 10;
    const int d = col & 1023;

    const float* __restrict__ base =
        x + ((size_t)b * N_DIM + (size_t)half * HALF_N) * D_DIM + d;
    const float* __restrict__ p = base;

    float top[K_TOP];
#pragma unroll
    for (int j = 0; j < K_TOP; ++j) top[j] = T_INIT;
    int cnt = 0;

    float bufA[U], bufB[U];
    load_batch(bufA, p);
    p += (size_t)U * D_DIM;

#pragma unroll 1
    for (int pair = 0; pair < NBATCH / 2 - 1; ++pair) {
        load_batch(bufB, p);
        p += (size_t)U * D_DIM;
        process_batch(top, bufA, cnt);
        load_batch(bufA, p);
        p += (size_t)U * D_DIM;
        process_batch(top, bufB, cnt);
    }
    load_batch(bufB, p);
    process_batch(top, bufA, cnt);
    process_batch(top, bufB, cnt);

    // Rare fallback: threshold seed captured fewer than 16 values -> this
    // half's true top-16 may dip below T_INIT. Rescan with -inf seed.
    if (cnt < K_TOP) {
#pragma unroll
        for (int j = 0; j < K_TOP; ++j) top[j] = -FLT_MAX;
        const float* q = base;
#pragma unroll 1
        for (int n = 0; n < HALF_N; ++n) {
            float v = __ldcs(q);
            q += D_DIM;
            if (v > top[K_TOP - 1]) insert_sorted(top, v);
        }
    }

    // Upper halves publish; lower halves merge + mean.
    if (half == 1) {
#pragma unroll
        for (int j = 0; j < K_TOP; ++j) s_top[cidx][j] = top[j];
    }
    __syncthreads();
    if (half == 0) {
        float s = 0.0f;
#pragma unroll
        for (int j = 0; j < K_TOP; ++j)
            s += fmaxf(top[j], s_top[cidx][K_TOP - 1 - j]);
        out[col] = s * (1.0f / K_TOP);
    }
}

extern "C" void kernel_launch(void* const* d_in, const int* in_sizes, int n_in,
                              void* d_out, int out_size) {
    const float* x = (const float*)d_in[0];
    float* out = (float*)d_out;
    topk_mean_kernel<<<NBLK, TPB>>>(x, out);
}

// round 17
// speedup vs baseline: 4.6703x; 4.6703x over previous
#include <cuda_runtime.h>
#include <float.h>

// x: [B=64, N=4096, D=1024] fp32. Per (b,d): top-16 along N, then mean -> out [B, D].
//
// Two-phase filter-then-select:
//  Phase 1: 4 threads/column stream the data and compact values > T=2.0
//           (p=2.28% -> ~93 candidates/column) into device scratch.
//           Pure streaming: ~4 issues/element, DRAM-bound.
//  Phase 2: 1 thread/column does exact top-16 over the ~93 candidates
//           (coalesced reads), then mean. Unconditional fallback: if a
//           segment overflowed CAP or total<16 (both ~1e-11 events), the
//           thread rescans its whole column with BATCHED loads (no serial
//           latency chain -> no straggler tail like R16).

#define B_DIM 64
#define N_DIM 4096
#define D_DIM 1024
#define K_TOP 16
#define NCOL (B_DIM * D_DIM)      // 65536
#define SEGS 4
#define SEG_N (N_DIM / SEGS)      // 1024
#define CAP 64
#define T_FILT 2.0f
#define U 16

// Scratch: [seg][slot][col] -> phase-2 reads are coalesced across col.
__device__ float g_scratch[SEGS * CAP * NCOL];          // 64 MB
__device__ unsigned g_cnt[SEGS * NCOL];                 // 1 MB

// ---------------------------------------------------------------- Phase 1
#define P1_TPB 256
#define P1_NTHREADS (SEGS * NCOL)                       // 262144

__global__ __launch_bounds__(P1_TPB, 8)
void filter_kernel(const float* __restrict__ x) {
    const int t = blockIdx.x * P1_TPB + threadIdx.x;    // [0, 262144)
    const int seg = t >> 16;
    const int col = t & (NCOL - 1);
    const int b = col >> 10;
    const int d = col & 1023;

    const float* __restrict__ p =
        x + ((size_t)b * N_DIM + (size_t)seg * SEG_N) * D_DIM + d;
    float* __restrict__ wp = g_scratch + (size_t)(seg * CAP) * NCOL + col;

    unsigned q = 0;   // unclamped count of qualifiers

#pragma unroll 1
    for (int n = 0; n < SEG_N; n += U) {
        float buf[U];
#pragma unroll
        for (int u = 0; u < U; ++u)
            buf[u] = __ldcs(p + (size_t)u * D_DIM);
        p += (size_t)U * D_DIM;

#pragma unroll
        for (int u = 0; u < U; ++u) {
            float v = buf[u];
            bool gt = v > T_FILT;
            if (gt && q < CAP) {
                *wp = v;
                wp += NCOL;
            }
            q += (unsigned)gt;
        }
    }
    g_cnt[seg * NCOL + col] = q;
}

// ---------------------------------------------------------------- Phase 2
#define P2_TPB 256

__device__ __forceinline__ void insert_sorted(float* __restrict__ top, float v) {
    float nt[K_TOP];
    nt[0] = fmaxf(top[0], v);
#pragma unroll
    for (int j = 1; j < K_TOP; ++j)
        nt[j] = fmaxf(top[j], fminf(top[j - 1], v));
#pragma unroll
    for (int j = 0; j < K_TOP; ++j) top[j] = nt[j];
}

__global__ __launch_bounds__(P2_TPB, 8)
void select_kernel(const float* __restrict__ x, float* __restrict__ out) {
    const int col = blockIdx.x * P2_TPB + threadIdx.x;  // [0, 65536)
    const int b = col >> 10;
    const int d = col & 1023;

    unsigned q[SEGS];
    unsigned total = 0;
    bool bad = false;
#pragma unroll
    for (int s = 0; s < SEGS; ++s) {
        q[s] = g_cnt[s * NCOL + col];
        total += q[s];
        if (q[s] > CAP) bad = true;
    }
    if (total < K_TOP) bad = true;

    float top[K_TOP];
#pragma unroll
    for (int j = 0; j < K_TOP; ++j) top[j] = -FLT_MAX;

    if (!bad) {
#pragma unroll 1
        for (int s = 0; s < SEGS; ++s) {
            const float* rp = g_scratch + (size_t)(s * CAP) * NCOL + col;
            const int m = (int)q[s];
#pragma unroll 1
            for (int i = 0; i < m; ++i) {
                float v = *rp;
                rp += NCOL;
                if (v > top[K_TOP - 1]) insert_sorted(top, v);
            }
        }
    } else {
        // Statistically-never fallback: full column rescan with batched loads
        // (MLP=16) so even a lone straggler finishes in ~tens of us.
        const float* p = x + (size_t)b * N_DIM * D_DIM + d;
#pragma unroll 1
        for (int n = 0; n < N_DIM; n += U) {
            float buf[U];
#pragma unroll
            for (int u = 0; u < U; ++u)
                buf[u] = __ldcs(p + (size_t)u * D_DIM);
            p += (size_t)U * D_DIM;
#pragma unroll
            for (int u = 0; u < U; ++u)
                if (buf[u] > top[K_TOP - 1]) insert_sorted(top, buf[u]);
        }
    }

    float sum = 0.0f;
#pragma unroll
    for (int j = 0; j < K_TOP; ++j) sum += top[j];
    out[col] = sum * (1.0f / K_TOP);
}

extern "C" void kernel_launch(void* const* d_in, const int* in_sizes, int n_in,
                              void* d_out, int out_size) {
    const float* x = (const float*)d_in[0];
    float* out = (float*)d_out;
    filter_kernel<<<P1_NTHREADS / P1_TPB, P1_TPB>>>(x);
    select_kernel<<<NCOL / P2_TPB, P2_TPB>>>(x, out);
}